// round 16
// baseline (speedup 1.0000x reference)
#include <cuda_runtime.h>
#include <cuda_fp16.h>
#include <cstdint>

#define N_NODES 100000
#define N_EDGES 1600000
#define D 64
#define SCAN_TILE 1024
#define SCAN_NBLK ((N_NODES + SCAN_TILE - 1) / SCAN_TILE)   // 98

// ---------------- scratch (no allocs allowed) ----------------
__device__ __half g_h16[(size_t)N_NODES * D];      // layer-1 output (fp16)
__device__ __half g_projL16[(size_t)N_NODES * D];  // feat @ Wl^T (fp16, gathered per-edge)
__device__ __half g_projR16[(size_t)N_NODES * D];  // layer-1 feat @ Wr^T (fp16)
__device__ float  g_projR[(size_t)N_NODES * D];    // layer-2 feat @ Wr^T (fp32)
__device__ int    g_deg[N_NODES];
__device__ int    g_off[N_NODES];
__device__ int    g_pos[N_NODES];
__device__ int    g_csr[N_EDGES];
__device__ unsigned long long g_status[SCAN_NBLK];  // lookback: flag<<32 | sum

// ---------------- mma.sync helpers (base PTX, works on sm_103 non-'a') ----------------
static __device__ __forceinline__ uint32_t smem_u32(const void* p) {
    uint32_t a;
    asm("{ .reg .u64 t; cvta.to.shared.u64 t, %1; cvt.u32.u64 %0, t; }"
        : "=r"(a) : "l"(p));
    return a;
}
static __device__ __forceinline__ void ldsm_x4(uint32_t* r, uint32_t addr) {
    asm volatile("ldmatrix.sync.aligned.m8n8.x4.shared.b16 {%0,%1,%2,%3}, [%4];"
                 : "=r"(r[0]), "=r"(r[1]), "=r"(r[2]), "=r"(r[3]) : "r"(addr));
}
static __device__ __forceinline__ void mma16816(float* c, const uint32_t* a,
                                                const uint32_t* b) {
    asm volatile(
        "mma.sync.aligned.m16n8k16.row.col.f32.f16.f16.f32 "
        "{%0,%1,%2,%3}, {%4,%5,%6,%7}, {%8,%9}, {%0,%1,%2,%3};"
        : "+f"(c[0]), "+f"(c[1]), "+f"(c[2]), "+f"(c[3])
        : "r"(a[0]), "r"(a[1]), "r"(a[2]), "r"(a[3]), "r"(b[0]), "r"(b[1]));
}

// ---------------- inline dtype detection (per-warp) ----------------
__device__ __forceinline__ int warp_is64(const unsigned* __restrict__ w) {
    unsigned v = w[2 * (threadIdx.x & 31) + 1];
    return __ballot_sync(0xffffffffu, v != 0) == 0;
}
__device__ __forceinline__ int edge_at(const void* ei, long long pos, int is64) {
    return is64 ? (int)((const long long*)ei)[pos]
                : ((const int*)ei)[pos];
}

// ---------------- CSR build ----------------
__global__ __launch_bounds__(256) void hist_kernel(const void* __restrict__ ei) {
    int is64 = warp_is64((const unsigned*)ei);
    int e = blockIdx.x * 256 + threadIdx.x;
    if (e >= N_EDGES) return;
    int dst = edge_at(ei, (long long)N_EDGES + e, is64);
    atomicAdd(&g_deg[dst], 1);
}

__global__ __launch_bounds__(256) void scan_lookback_kernel() {
    const unsigned FULL = 0xffffffffu;
    int b = blockIdx.x;
    int base = b * SCAN_TILE;
    int idx0 = base + threadIdx.x * 4;
    int v[4];
#pragma unroll
    for (int j = 0; j < 4; j++)
        v[j] = (idx0 + j < N_NODES) ? g_deg[idx0 + j] : 0;
    int tsum = v[0] + v[1] + v[2] + v[3];

    int lane = threadIdx.x & 31, wid = threadIdx.x >> 5;
    int s = tsum;
#pragma unroll
    for (int o = 1; o < 32; o <<= 1) {
        int t = __shfl_up_sync(FULL, s, o);
        if (lane >= o) s += t;
    }
    __shared__ int wsum[8];
    __shared__ int sprefix;
    if (lane == 31) wsum[wid] = s;
    __syncthreads();
    if (wid == 0) {
        int ws = (lane < 8) ? wsum[lane] : 0;
#pragma unroll
        for (int o = 1; o < 8; o <<= 1) {
            int t = __shfl_up_sync(FULL, ws, o);
            if (lane >= o) ws += t;
        }
        if (lane < 8) wsum[lane] = ws;
    }
    __syncthreads();
    int excl = s - tsum + (wid > 0 ? wsum[wid - 1] : 0);
    int total = wsum[7];

    if (wid == 7) {
        if (lane == 31) {
            unsigned long long pk =
                ((unsigned long long)(b == 0 ? 2u : 1u) << 32) | (unsigned)total;
            atomicExch(&g_status[b], pk);
        }
        int prefix = 0;
        if (b > 0) {
            int w = 0;
            bool done = false;
            while (!done) {
                int idx = b - 32 * (w + 1) + lane;
                int flag, val;
                do {
                    if (idx >= 0) {
                        unsigned long long st = atomicAdd(&g_status[idx], 0ULL);
                        flag = (int)(st >> 32);
                        val = (int)(st & 0xffffffffu);
                    } else { flag = 2; val = 0; }
                } while (__ballot_sync(FULL, flag == 0));
                unsigned m2 = __ballot_sync(FULL, flag == 2);
                int contrib;
                if (m2) {
                    int h = 31 - __clz(m2);
                    contrib = (lane >= h) ? val : 0;
                    done = true;
                } else {
                    contrib = val;
                    w++;
                }
#pragma unroll
                for (int o = 16; o; o >>= 1)
                    contrib += __shfl_down_sync(FULL, contrib, o);
                prefix += __shfl_sync(FULL, contrib, 0);
            }
            if (lane == 31)
                atomicExch(&g_status[b],
                           (2ULL << 32) | (unsigned)(prefix + total));
        }
        if (lane == 0) sprefix = prefix;
    }
    __syncthreads();

    int run = excl + sprefix;
#pragma unroll
    for (int j = 0; j < 4; j++) {
        if (idx0 + j < N_NODES) { g_off[idx0 + j] = run; g_pos[idx0 + j] = run; }
        run += v[j];
    }
}

__global__ __launch_bounds__(256) void scatter_kernel(const void* __restrict__ ei) {
    int is64 = warp_is64((const unsigned*)ei);
    int e = blockIdx.x * 256 + threadIdx.x;
    if (e >= N_EDGES) return;
    int src = edge_at(ei, e, is64);
    int dst = edge_at(ei, (long long)N_EDGES + e, is64);
    int p = atomicAdd(&g_pos[dst], 1);
    g_csr[p] = src;
}

// ---------------- tensor-core (HMMA) projection (R13-proven form) ----------------
#define SPAD 72   // half-stride per row (64 + 8 pad)

__global__ __launch_bounds__(256) void proj_mma_kernel(const float* __restrict__ feat32,
                                                       const float* __restrict__ Wl,
                                                       const float* __restrict__ Wr,
                                                       int layer1) {
    __shared__ __half As[128][SPAD];
    __shared__ __half Bs[128][SPAD];

    int tid = threadIdx.x;
    int nb = blockIdx.x * 128;

    // load: thread -> (row, k-half of 32 elements)
    {
        int r = tid >> 1, h = tid & 1;
        {   // A: node features
            int node = nb + r;
            float4 outv[4];
            if (node < N_NODES) {
                if (layer1) {
                    const float* src = feat32 + (size_t)node * D + h * 32;
                    __half2 tmp[16];
#pragma unroll
                    for (int q = 0; q < 8; q++) {
                        float4 f = *(const float4*)(src + q * 4);
                        tmp[2 * q + 0] = __floats2half2_rn(f.x, f.y);
                        tmp[2 * q + 1] = __floats2half2_rn(f.z, f.w);
                    }
#pragma unroll
                    for (int q = 0; q < 4; q++) outv[q] = ((float4*)tmp)[q];
                } else {
                    const float4* src = (const float4*)(g_h16 + (size_t)node * D + h * 32);
#pragma unroll
                    for (int q = 0; q < 4; q++) outv[q] = src[q];
                }
            } else {
#pragma unroll
                for (int q = 0; q < 4; q++) outv[q] = make_float4(0.f, 0.f, 0.f, 0.f);
            }
            float4* dst = (float4*)&As[r][h * 32];
#pragma unroll
            for (int q = 0; q < 4; q++) dst[q] = outv[q];
        }
        {   // B: weight rows (output col c): Wl rows 0-63, Wr rows 64-127
            int c = r;
            const float* src = ((c < 64) ? (Wl + (size_t)c * 64)
                                         : (Wr + (size_t)(c - 64) * 64)) + h * 32;
            __half2 tmp[16];
#pragma unroll
            for (int q = 0; q < 8; q++) {
                float4 f = *(const float4*)(src + q * 4);
                tmp[2 * q + 0] = __floats2half2_rn(f.x, f.y);
                tmp[2 * q + 1] = __floats2half2_rn(f.z, f.w);
            }
            float4* dst = (float4*)&Bs[r][h * 32];
#pragma unroll
            for (int q = 0; q < 4; q++) dst[q] = ((float4*)tmp)[q];
        }
    }
    __syncthreads();

    int wid = tid >> 5, lane = tid & 31;
    int wm = wid & 3;       // M chunk (32 nodes)
    int wn = wid >> 2;      // N chunk (64 cols): 0 -> projL, 1 -> projR

    uint32_t a_base = smem_u32(&As[0][0]);
    uint32_t b_base = smem_u32(&Bs[0][0]);

    float acc[2][8][4];
#pragma unroll
    for (int i = 0; i < 2; i++)
#pragma unroll
        for (int t = 0; t < 8; t++)
#pragma unroll
            for (int q = 0; q < 4; q++) acc[i][t][q] = 0.f;

#pragma unroll
    for (int kc = 0; kc < 4; kc++) {
        uint32_t af[2][4];
#pragma unroll
        for (int i = 0; i < 2; i++) {
            int row = wm * 32 + i * 16 + (lane & 15);
            int ko = kc * 16 + (lane >> 4) * 8;
            ldsm_x4(af[i], a_base + (uint32_t)(row * SPAD + ko) * 2);
        }
#pragma unroll
        for (int j = 0; j < 4; j++) {
            int m = lane >> 3;
            int n = wn * 64 + j * 16 + ((m & 2) ? 8 : 0) + (lane & 7);
            int ko = kc * 16 + ((m & 1) ? 8 : 0);
            uint32_t bf[4];
            ldsm_x4(bf, b_base + (uint32_t)(n * SPAD + ko) * 2);
#pragma unroll
            for (int i = 0; i < 2; i++) {
                mma16816(acc[i][j * 2 + 0], af[i], bf + 0);
                mma16816(acc[i][j * 2 + 1], af[i], bf + 2);
            }
        }
    }

    // epilogue: C frag (row = lane>>2 [+8], cols = (lane&3)*2 +0/1)
    int gr = lane >> 2, cp = (lane & 3) * 2;
#pragma unroll
    for (int i = 0; i < 2; i++) {
#pragma unroll
        for (int t = 0; t < 8; t++) {
            int col = wn * 64 + t * 8 + cp;   // 0-63 projL, 64-127 projR
#pragma unroll
            for (int hrow = 0; hrow < 2; hrow++) {
                int r = wm * 32 + i * 16 + gr + hrow * 8;
                int node = nb + r;
                if (node < N_NODES) {
                    float v0 = acc[i][t][hrow * 2 + 0];
                    float v1 = acc[i][t][hrow * 2 + 1];
                    if (wn == 0) {
                        *(__half2*)(g_projL16 + (size_t)node * D + col) =
                            __floats2half2_rn(v0, v1);
                    } else if (layer1) {
                        *(__half2*)(g_projR16 + (size_t)node * D + (col - 64)) =
                            __floats2half2_rn(v0, v1);
                    } else {
                        *(float2*)(g_projR + (size_t)node * D + (col - 64)) =
                            make_float2(v0, v1);
                    }
                }
            }
        }
    }
}

// ---------------- combine: out_i = mean_j projL_j + projR_i + b (+relu) ----------------
// 8 threads/node, one 16B fp16 chunk each; 4-neighbor batches with explicit
// prefetch of the NEXT batch's indices before accumulating the current one.
__device__ __forceinline__ void acc_h8(float a[8], float4 raw) {
    __half2* hp = (__half2*)&raw;
    float2 f0 = __half22float2(hp[0]);
    float2 f1 = __half22float2(hp[1]);
    float2 f2 = __half22float2(hp[2]);
    float2 f3 = __half22float2(hp[3]);
    a[0] += f0.x; a[1] += f0.y; a[2] += f1.x; a[3] += f1.y;
    a[4] += f2.x; a[5] += f2.y; a[6] += f3.x; a[7] += f3.y;
}

__global__ __launch_bounds__(256) void agg_combine_kernel(const float* __restrict__ b,
                                                          float* __restrict__ out_param,
                                                          int layer1) {
    int t = blockIdx.x * 256 + threadIdx.x;
    int node = t >> 3;
    int c = t & 7;               // 8 cols each
    if (node >= N_NODES) return;

    const int beg = g_off[node];
    const int n = g_deg[node];
    const int nb4 = n & ~3;
    const __half* fp = g_projL16 + c * 8;
    float a[8] = {0.f, 0.f, 0.f, 0.f, 0.f, 0.f, 0.f, 0.f};

    int i0 = 0, i1 = 0, i2 = 0, i3 = 0;
    if (nb4 > 0) {
        i0 = g_csr[beg + 0]; i1 = g_csr[beg + 1];
        i2 = g_csr[beg + 2]; i3 = g_csr[beg + 3];
    }
    for (int j = 0; j < nb4; ) {
        int s0 = i0, s1 = i1, s2 = i2, s3 = i3;
        j += 4;
        if (j < nb4) {                       // prefetch next batch's indices
            i0 = g_csr[beg + j + 0]; i1 = g_csr[beg + j + 1];
            i2 = g_csr[beg + j + 2]; i3 = g_csr[beg + j + 3];
        }
        float4 r0 = *(const float4*)(fp + (size_t)s0 * D);
        float4 r1 = *(const float4*)(fp + (size_t)s1 * D);
        float4 r2 = *(const float4*)(fp + (size_t)s2 * D);
        float4 r3 = *(const float4*)(fp + (size_t)s3 * D);
        acc_h8(a, r0); acc_h8(a, r1); acc_h8(a, r2); acc_h8(a, r3);
    }
    for (int j = nb4; j < n; j++) {
        int sidx = g_csr[beg + j];
        acc_h8(a, *(const float4*)(fp + (size_t)sidx * D));
    }
    float inv = 1.0f / fmaxf((float)n, 1.0f);
    float4 bv0 = *(const float4*)(b + c * 8);
    float4 bv1 = *(const float4*)(b + c * 8 + 4);

    if (layer1) {
        float4 xr = *(const float4*)(g_projR16 + (size_t)node * D + c * 8);
        float xf[8];
        {
            __half2* hp = (__half2*)&xr;
            float2 f0 = __half22float2(hp[0]);
            float2 f1 = __half22float2(hp[1]);
            float2 f2 = __half22float2(hp[2]);
            float2 f3 = __half22float2(hp[3]);
            xf[0] = f0.x; xf[1] = f0.y; xf[2] = f1.x; xf[3] = f1.y;
            xf[4] = f2.x; xf[5] = f2.y; xf[6] = f3.x; xf[7] = f3.y;
        }
        float o[8];
        o[0] = a[0] * inv + xf[0] + bv0.x;
        o[1] = a[1] * inv + xf[1] + bv0.y;
        o[2] = a[2] * inv + xf[2] + bv0.z;
        o[3] = a[3] * inv + xf[3] + bv0.w;
        o[4] = a[4] * inv + xf[4] + bv1.x;
        o[5] = a[5] * inv + xf[5] + bv1.y;
        o[6] = a[6] * inv + xf[6] + bv1.z;
        o[7] = a[7] * inv + xf[7] + bv1.w;
        __half2 h[4];
#pragma unroll
        for (int q = 0; q < 4; q++)
            h[q] = __floats2half2_rn(fmaxf(o[2 * q], 0.f), fmaxf(o[2 * q + 1], 0.f));
        *(float4*)(g_h16 + (size_t)node * D + c * 8) = *(float4*)h;
    } else {
        float4 xr0 = *(const float4*)(g_projR + (size_t)node * D + c * 8);
        float4 xr1 = *(const float4*)(g_projR + (size_t)node * D + c * 8 + 4);
        float4 o0, o1;
        o0.x = a[0] * inv + xr0.x + bv0.x;
        o0.y = a[1] * inv + xr0.y + bv0.y;
        o0.z = a[2] * inv + xr0.z + bv0.z;
        o0.w = a[3] * inv + xr0.w + bv0.w;
        o1.x = a[4] * inv + xr1.x + bv1.x;
        o1.y = a[5] * inv + xr1.y + bv1.y;
        o1.z = a[6] * inv + xr1.z + bv1.z;
        o1.w = a[7] * inv + xr1.w + bv1.w;
        *(float4*)(out_param + (size_t)node * D + c * 8) = o0;
        *(float4*)(out_param + (size_t)node * D + c * 8 + 4) = o1;
    }
}

// ---------------- launch (R13 topology: build fork only) ----------------
extern "C" void kernel_launch(void* const* d_in, const int* in_sizes, int n_in,
                              void* d_out, int out_size) {
    const float* x   = (const float*)d_in[0];
    const void*  ei  = d_in[1];
    const float* W1l = (const float*)d_in[2];
    const float* W1r = (const float*)d_in[3];
    const float* b1  = (const float*)d_in[4];
    const float* W2l = (const float*)d_in[5];
    const float* W2r = (const float*)d_in[6];
    const float* b2  = (const float*)d_in[7];
    float* out = (float*)d_out;

    static cudaStream_t s_side = nullptr;
    static cudaEvent_t ev_fork = nullptr, ev_join = nullptr;
    if (!s_side) {
        cudaStreamCreateWithFlags(&s_side, cudaStreamNonBlocking);
        cudaEventCreateWithFlags(&ev_fork, cudaEventDisableTiming);
        cudaEventCreateWithFlags(&ev_join, cudaEventDisableTiming);
    }

    const int E_BLOCKS   = (N_EDGES + 255) / 256;
    const int MM_BLOCKS  = (N_NODES + 127) / 128;
    const int AGG_BLOCKS = (N_NODES * 8 + 255) / 256;

    void* p_deg = nullptr;
    void* p_st  = nullptr;
    cudaGetSymbolAddress(&p_deg, g_deg);
    cudaGetSymbolAddress(&p_st, g_status);

    // fork: CSR build on side stream, concurrent with layer-1 projection
    cudaEventRecord(ev_fork, 0);
    cudaStreamWaitEvent(s_side, ev_fork, 0);
    cudaMemsetAsync(p_deg, 0, N_NODES * sizeof(int), s_side);
    cudaMemsetAsync(p_st, 0, SCAN_NBLK * sizeof(unsigned long long), s_side);
    hist_kernel<<<E_BLOCKS, 256, 0, s_side>>>(ei);
    scan_lookback_kernel<<<SCAN_NBLK, 256, 0, s_side>>>();
    scatter_kernel<<<E_BLOCKS, 256, 0, s_side>>>(ei);
    cudaEventRecord(ev_join, s_side);

    // layer-1 projection (independent of CSR)
    proj_mma_kernel<<<MM_BLOCKS, 256>>>(x, W1l, W1r, 1);

    // join, then serial chain
    cudaStreamWaitEvent(0, ev_join, 0);
    agg_combine_kernel<<<AGG_BLOCKS, 256>>>(b1, nullptr, 1);        // -> g_h16 (relu)
    proj_mma_kernel<<<MM_BLOCKS, 256>>>(nullptr, W2l, W2r, 0);      // h16 proj
    agg_combine_kernel<<<AGG_BLOCKS, 256>>>(b2, out, 0);            // -> d_out
}

// round 17
// speedup vs baseline: 1.1694x; 1.1694x over previous
#include <cuda_runtime.h>
#include <cuda_fp16.h>
#include <cstdint>

#define N_NODES 100000
#define N_EDGES 1600000
#define D 64
#define SCAN_TILE 1024
#define SCAN_NBLK ((N_NODES + SCAN_TILE - 1) / SCAN_TILE)   // 98

// ---------------- scratch (no allocs allowed) ----------------
__device__ __half g_h16[(size_t)N_NODES * D];      // layer-1 output (fp16)
__device__ __half g_projL16[(size_t)N_NODES * D];  // feat @ Wl^T (fp16, gathered per-edge)
__device__ __half g_projR16[(size_t)N_NODES * D];  // layer-1 feat @ Wr^T (fp16)
__device__ float  g_projR[(size_t)N_NODES * D];    // layer-2 feat @ Wr^T (fp32)
__device__ int    g_deg[N_NODES];
__device__ int    g_off[N_NODES];
__device__ int    g_pos[N_NODES];
__device__ int    g_csr[N_EDGES];
__device__ unsigned long long g_status[SCAN_NBLK];  // lookback: flag<<32 | sum

// ---------------- mma.sync helpers (base PTX, works on sm_103 non-'a') ----------------
static __device__ __forceinline__ uint32_t smem_u32(const void* p) {
    uint32_t a;
    asm("{ .reg .u64 t; cvta.to.shared.u64 t, %1; cvt.u32.u64 %0, t; }"
        : "=r"(a) : "l"(p));
    return a;
}
static __device__ __forceinline__ void ldsm_x4(uint32_t* r, uint32_t addr) {
    asm volatile("ldmatrix.sync.aligned.m8n8.x4.shared.b16 {%0,%1,%2,%3}, [%4];"
                 : "=r"(r[0]), "=r"(r[1]), "=r"(r[2]), "=r"(r[3]) : "r"(addr));
}
static __device__ __forceinline__ void mma16816(float* c, const uint32_t* a,
                                                const uint32_t* b) {
    asm volatile(
        "mma.sync.aligned.m16n8k16.row.col.f32.f16.f16.f32 "
        "{%0,%1,%2,%3}, {%4,%5,%6,%7}, {%8,%9}, {%0,%1,%2,%3};"
        : "+f"(c[0]), "+f"(c[1]), "+f"(c[2]), "+f"(c[3])
        : "r"(a[0]), "r"(a[1]), "r"(a[2]), "r"(a[3]), "r"(b[0]), "r"(b[1]));
}

// ---------------- inline dtype detection (per-warp) ----------------
__device__ __forceinline__ int warp_is64(const unsigned* __restrict__ w) {
    unsigned v = w[2 * (threadIdx.x & 31) + 1];
    return __ballot_sync(0xffffffffu, v != 0) == 0;
}
__device__ __forceinline__ int edge_at(const void* ei, long long pos, int is64) {
    return is64 ? (int)((const long long*)ei)[pos]
                : ((const int*)ei)[pos];
}

// ---------------- CSR build ----------------
__global__ __launch_bounds__(256) void hist_kernel(const void* __restrict__ ei) {
    int is64 = warp_is64((const unsigned*)ei);
    int e = blockIdx.x * 256 + threadIdx.x;
    if (e >= N_EDGES) return;
    int dst = edge_at(ei, (long long)N_EDGES + e, is64);
    atomicAdd(&g_deg[dst], 1);
}

__global__ __launch_bounds__(256) void scan_lookback_kernel() {
    const unsigned FULL = 0xffffffffu;
    int b = blockIdx.x;
    int base = b * SCAN_TILE;
    int idx0 = base + threadIdx.x * 4;
    int v[4];
#pragma unroll
    for (int j = 0; j < 4; j++)
        v[j] = (idx0 + j < N_NODES) ? g_deg[idx0 + j] : 0;
    int tsum = v[0] + v[1] + v[2] + v[3];

    int lane = threadIdx.x & 31, wid = threadIdx.x >> 5;
    int s = tsum;
#pragma unroll
    for (int o = 1; o < 32; o <<= 1) {
        int t = __shfl_up_sync(FULL, s, o);
        if (lane >= o) s += t;
    }
    __shared__ int wsum[8];
    __shared__ int sprefix;
    if (lane == 31) wsum[wid] = s;
    __syncthreads();
    if (wid == 0) {
        int ws = (lane < 8) ? wsum[lane] : 0;
#pragma unroll
        for (int o = 1; o < 8; o <<= 1) {
            int t = __shfl_up_sync(FULL, ws, o);
            if (lane >= o) ws += t;
        }
        if (lane < 8) wsum[lane] = ws;
    }
    __syncthreads();
    int excl = s - tsum + (wid > 0 ? wsum[wid - 1] : 0);
    int total = wsum[7];

    if (wid == 7) {
        if (lane == 31) {
            unsigned long long pk =
                ((unsigned long long)(b == 0 ? 2u : 1u) << 32) | (unsigned)total;
            atomicExch(&g_status[b], pk);
        }
        int prefix = 0;
        if (b > 0) {
            int w = 0;
            bool done = false;
            while (!done) {
                int idx = b - 32 * (w + 1) + lane;
                int flag, val;
                do {
                    if (idx >= 0) {
                        unsigned long long st = atomicAdd(&g_status[idx], 0ULL);
                        flag = (int)(st >> 32);
                        val = (int)(st & 0xffffffffu);
                    } else { flag = 2; val = 0; }
                } while (__ballot_sync(FULL, flag == 0));
                unsigned m2 = __ballot_sync(FULL, flag == 2);
                int contrib;
                if (m2) {
                    int h = 31 - __clz(m2);
                    contrib = (lane >= h) ? val : 0;
                    done = true;
                } else {
                    contrib = val;
                    w++;
                }
#pragma unroll
                for (int o = 16; o; o >>= 1)
                    contrib += __shfl_down_sync(FULL, contrib, o);
                prefix += __shfl_sync(FULL, contrib, 0);
            }
            if (lane == 31)
                atomicExch(&g_status[b],
                           (2ULL << 32) | (unsigned)(prefix + total));
        }
        if (lane == 0) sprefix = prefix;
    }
    __syncthreads();

    int run = excl + sprefix;
#pragma unroll
    for (int j = 0; j < 4; j++) {
        if (idx0 + j < N_NODES) { g_off[idx0 + j] = run; g_pos[idx0 + j] = run; }
        run += v[j];
    }
}

__global__ __launch_bounds__(256) void scatter_kernel(const void* __restrict__ ei) {
    int is64 = warp_is64((const unsigned*)ei);
    int e = blockIdx.x * 256 + threadIdx.x;
    if (e >= N_EDGES) return;
    int src = edge_at(ei, e, is64);
    int dst = edge_at(ei, (long long)N_EDGES + e, is64);
    int p = atomicAdd(&g_pos[dst], 1);
    g_csr[p] = src;
}

// ---------------- tensor-core (HMMA) projection ----------------
// projL(fp16)|projR = feat @ [Wl|Wr]^T per 128-node block.
// 256 threads = 8 warps in 4(M) x 2(N) grid; each warp 32 nodes x 64 cols.
// Load phase uses item-order mapping: warp lanes span contiguous 512B
// (4 lines) per LDG instead of 32 scattered lines.
#define SPAD 72   // half-stride per row (64 + 8 pad)

__global__ __launch_bounds__(256) void proj_mma_kernel(const float* __restrict__ feat32,
                                                       const float* __restrict__ Wl,
                                                       const float* __restrict__ Wr,
                                                       int layer1) {
    __shared__ __half As[128][SPAD];
    __shared__ __half Bs[128][SPAD];

    int tid = threadIdx.x;
    int nb = blockIdx.x * 128;

    // ---- A: node features (coalesced item mapping) ----
    if (layer1) {
        // 128 rows x 16 float4 chunks (fp32 rows, 256B)
#pragma unroll
        for (int it = 0; it < 8; it++) {
            int item = it * 256 + tid;
            int r = item >> 4, ch = item & 15;
            int node = nb + r;
            float4 f = make_float4(0.f, 0.f, 0.f, 0.f);
            if (node < N_NODES)
                f = ((const float4*)(feat32 + (size_t)node * D))[ch];
            __half2 h2[2];
            h2[0] = __floats2half2_rn(f.x, f.y);
            h2[1] = __floats2half2_rn(f.z, f.w);
            *(float2*)&As[r][ch * 4] = *(float2*)h2;     // 8B STS
        }
    } else {
        // 128 rows x 8 float4 chunks (fp16 rows, 128B)
#pragma unroll
        for (int it = 0; it < 4; it++) {
            int item = it * 256 + tid;
            int r = item >> 3, ch = item & 7;
            int node = nb + r;
            float4 v = make_float4(0.f, 0.f, 0.f, 0.f);
            if (node < N_NODES)
                v = ((const float4*)(g_h16 + (size_t)node * D))[ch];
            *(float4*)&As[r][ch * 8] = v;                // 16B STS
        }
    }
    // ---- B: weight rows (coalesced item mapping) ----
#pragma unroll
    for (int it = 0; it < 8; it++) {
        int item = it * 256 + tid;
        int r = item >> 4, ch = item & 15;
        const float4* src = (const float4*)((r < 64) ? (Wl + (size_t)r * 64)
                                                     : (Wr + (size_t)(r - 64) * 64));
        float4 f = src[ch];
        __half2 h2[2];
        h2[0] = __floats2half2_rn(f.x, f.y);
        h2[1] = __floats2half2_rn(f.z, f.w);
        *(float2*)&Bs[r][ch * 4] = *(float2*)h2;         // 8B STS
    }
    __syncthreads();

    int wid = tid >> 5, lane = tid & 31;
    int wm = wid & 3;       // M chunk (32 nodes)
    int wn = wid >> 2;      // N chunk (64 cols): 0 -> projL, 1 -> projR

    uint32_t a_base = smem_u32(&As[0][0]);
    uint32_t b_base = smem_u32(&Bs[0][0]);

    float acc[2][8][4];
#pragma unroll
    for (int i = 0; i < 2; i++)
#pragma unroll
        for (int t = 0; t < 8; t++)
#pragma unroll
            for (int q = 0; q < 4; q++) acc[i][t][q] = 0.f;

#pragma unroll
    for (int kc = 0; kc < 4; kc++) {
        uint32_t af[2][4];
#pragma unroll
        for (int i = 0; i < 2; i++) {
            int row = wm * 32 + i * 16 + (lane & 15);
            int ko = kc * 16 + (lane >> 4) * 8;
            ldsm_x4(af[i], a_base + (uint32_t)(row * SPAD + ko) * 2);
        }
#pragma unroll
        for (int j = 0; j < 4; j++) {
            int m = lane >> 3;
            int n = wn * 64 + j * 16 + ((m & 2) ? 8 : 0) + (lane & 7);
            int ko = kc * 16 + ((m & 1) ? 8 : 0);
            uint32_t bf[4];
            ldsm_x4(bf, b_base + (uint32_t)(n * SPAD + ko) * 2);
#pragma unroll
            for (int i = 0; i < 2; i++) {
                mma16816(acc[i][j * 2 + 0], af[i], bf + 0);
                mma16816(acc[i][j * 2 + 1], af[i], bf + 2);
            }
        }
    }

    // epilogue: C frag (row = lane>>2 [+8], cols = (lane&3)*2 +0/1)
    int gr = lane >> 2, cp = (lane & 3) * 2;
#pragma unroll
    for (int i = 0; i < 2; i++) {
#pragma unroll
        for (int t = 0; t < 8; t++) {
            int col = wn * 64 + t * 8 + cp;   // 0-63 projL, 64-127 projR
#pragma unroll
            for (int hrow = 0; hrow < 2; hrow++) {
                int r = wm * 32 + i * 16 + gr + hrow * 8;
                int node = nb + r;
                if (node < N_NODES) {
                    float v0 = acc[i][t][hrow * 2 + 0];
                    float v1 = acc[i][t][hrow * 2 + 1];
                    if (wn == 0) {
                        *(__half2*)(g_projL16 + (size_t)node * D + col) =
                            __floats2half2_rn(v0, v1);
                    } else if (layer1) {
                        *(__half2*)(g_projR16 + (size_t)node * D + (col - 64)) =
                            __floats2half2_rn(v0, v1);
                    } else {
                        *(float2*)(g_projR + (size_t)node * D + (col - 64)) =
                            make_float2(v0, v1);
                    }
                }
            }
        }
    }
}

// ---------------- combine (EXACT R13 form): out_i = mean_j projL_j + projR_i + b ----------------
__device__ __forceinline__ void acc_h8(float a[8], float4 raw) {
    __half2* hp = (__half2*)&raw;
    float2 f0 = __half22float2(hp[0]);
    float2 f1 = __half22float2(hp[1]);
    float2 f2 = __half22float2(hp[2]);
    float2 f3 = __half22float2(hp[3]);
    a[0] += f0.x; a[1] += f0.y; a[2] += f1.x; a[3] += f1.y;
    a[4] += f2.x; a[5] += f2.y; a[6] += f3.x; a[7] += f3.y;
}

__global__ __launch_bounds__(256) void agg_combine_kernel(const float* __restrict__ b,
                                                          float* __restrict__ out_param,
                                                          int layer1) {
    int t = blockIdx.x * 256 + threadIdx.x;
    int node = t >> 3;
    int c = t & 7;               // 8 cols each
    if (node >= N_NODES) return;

    const int beg = g_off[node];
    const int n = g_deg[node];
    const __half* fp = g_projL16 + c * 8;
    float a[8] = {0.f, 0.f, 0.f, 0.f, 0.f, 0.f, 0.f, 0.f};
    int j = 0;
    for (; j + 4 <= n; j += 4) {
        int s0 = g_csr[beg + j + 0];
        int s1 = g_csr[beg + j + 1];
        int s2 = g_csr[beg + j + 2];
        int s3 = g_csr[beg + j + 3];
        float4 r0 = *(const float4*)(fp + (size_t)s0 * D);
        float4 r1 = *(const float4*)(fp + (size_t)s1 * D);
        float4 r2 = *(const float4*)(fp + (size_t)s2 * D);
        float4 r3 = *(const float4*)(fp + (size_t)s3 * D);
        acc_h8(a, r0); acc_h8(a, r1); acc_h8(a, r2); acc_h8(a, r3);
    }
    for (; j < n; j++) {
        int sidx = g_csr[beg + j];
        acc_h8(a, *(const float4*)(fp + (size_t)sidx * D));
    }
    float inv = 1.0f / fmaxf((float)n, 1.0f);
    float4 bv0 = *(const float4*)(b + c * 8);
    float4 bv1 = *(const float4*)(b + c * 8 + 4);

    if (layer1) {
        float4 xr = *(const float4*)(g_projR16 + (size_t)node * D + c * 8);
        float xf[8];
        {
            __half2* hp = (__half2*)&xr;
            float2 f0 = __half22float2(hp[0]);
            float2 f1 = __half22float2(hp[1]);
            float2 f2 = __half22float2(hp[2]);
            float2 f3 = __half22float2(hp[3]);
            xf[0] = f0.x; xf[1] = f0.y; xf[2] = f1.x; xf[3] = f1.y;
            xf[4] = f2.x; xf[5] = f2.y; xf[6] = f3.x; xf[7] = f3.y;
        }
        float o[8];
        o[0] = a[0] * inv + xf[0] + bv0.x;
        o[1] = a[1] * inv + xf[1] + bv0.y;
        o[2] = a[2] * inv + xf[2] + bv0.z;
        o[3] = a[3] * inv + xf[3] + bv0.w;
        o[4] = a[4] * inv + xf[4] + bv1.x;
        o[5] = a[5] * inv + xf[5] + bv1.y;
        o[6] = a[6] * inv + xf[6] + bv1.z;
        o[7] = a[7] * inv + xf[7] + bv1.w;
        __half2 h[4];
#pragma unroll
        for (int q = 0; q < 4; q++)
            h[q] = __floats2half2_rn(fmaxf(o[2 * q], 0.f), fmaxf(o[2 * q + 1], 0.f));
        *(float4*)(g_h16 + (size_t)node * D + c * 8) = *(float4*)h;
    } else {
        float4 xr0 = *(const float4*)(g_projR + (size_t)node * D + c * 8);
        float4 xr1 = *(const float4*)(g_projR + (size_t)node * D + c * 8 + 4);
        float4 o0, o1;
        o0.x = a[0] * inv + xr0.x + bv0.x;
        o0.y = a[1] * inv + xr0.y + bv0.y;
        o0.z = a[2] * inv + xr0.z + bv0.z;
        o0.w = a[3] * inv + xr0.w + bv0.w;
        o1.x = a[4] * inv + xr1.x + bv1.x;
        o1.y = a[5] * inv + xr1.y + bv1.y;
        o1.z = a[6] * inv + xr1.z + bv1.z;
        o1.w = a[7] * inv + xr1.w + bv1.w;
        *(float4*)(out_param + (size_t)node * D + c * 8) = o0;
        *(float4*)(out_param + (size_t)node * D + c * 8 + 4) = o1;
    }
}

// ---------------- launch (R13 topology: build fork only) ----------------
extern "C" void kernel_launch(void* const* d_in, const int* in_sizes, int n_in,
                              void* d_out, int out_size) {
    const float* x   = (const float*)d_in[0];
    const void*  ei  = d_in[1];
    const float* W1l = (const float*)d_in[2];
    const float* W1r = (const float*)d_in[3];
    const float* b1  = (const float*)d_in[4];
    const float* W2l = (const float*)d_in[5];
    const float* W2r = (const float*)d_in[6];
    const float* b2  = (const float*)d_in[7];
    float* out = (float*)d_out;

    static cudaStream_t s_side = nullptr;
    static cudaEvent_t ev_fork = nullptr, ev_join = nullptr;
    if (!s_side) {
        cudaStreamCreateWithFlags(&s_side, cudaStreamNonBlocking);
        cudaEventCreateWithFlags(&ev_fork, cudaEventDisableTiming);
        cudaEventCreateWithFlags(&ev_join, cudaEventDisableTiming);
    }

    const int E_BLOCKS   = (N_EDGES + 255) / 256;
    const int MM_BLOCKS  = (N_NODES + 127) / 128;
    const int AGG_BLOCKS = (N_NODES * 8 + 255) / 256;

    void* p_deg = nullptr;
    void* p_st  = nullptr;
    cudaGetSymbolAddress(&p_deg, g_deg);
    cudaGetSymbolAddress(&p_st, g_status);

    // fork: CSR build on side stream, concurrent with layer-1 projection
    cudaEventRecord(ev_fork, 0);
    cudaStreamWaitEvent(s_side, ev_fork, 0);
    cudaMemsetAsync(p_deg, 0, N_NODES * sizeof(int), s_side);
    cudaMemsetAsync(p_st, 0, SCAN_NBLK * sizeof(unsigned long long), s_side);
    hist_kernel<<<E_BLOCKS, 256, 0, s_side>>>(ei);
    scan_lookback_kernel<<<SCAN_NBLK, 256, 0, s_side>>>();
    scatter_kernel<<<E_BLOCKS, 256, 0, s_side>>>(ei);
    cudaEventRecord(ev_join, s_side);

    // layer-1 projection (independent of CSR)
    proj_mma_kernel<<<MM_BLOCKS, 256>>>(x, W1l, W1r, 1);

    // join, then serial chain
    cudaStreamWaitEvent(0, ev_join, 0);
    agg_combine_kernel<<<AGG_BLOCKS, 256>>>(b1, nullptr, 1);        // -> g_h16 (relu)
    proj_mma_kernel<<<MM_BLOCKS, 256>>>(nullptr, W2l, W2r, 0);      // h16 proj
    agg_combine_kernel<<<AGG_BLOCKS, 256>>>(b2, out, 0);            // -> d_out
}